// round 6
// baseline (speedup 1.0000x reference)
#include <cuda_runtime.h>
#include <math.h>

// Problem constants
#define Bb 16
#define Tt 16
#define Cc 64
#define HD 64
#define HW 1024
#define IMW 32
#define NT 128
#define SROW 36
#define PLANE (34*SROW)   // 1224 floats per padded plane

// Scratch (device globals: no allocation allowed)
__device__ float g_h   [Bb*HD*HW];
__device__ float g_hode[Bb*HD*HW];
__device__ float g_rh  [Bb*HD*HW];
__device__ float g_u   [Bb*HD*HW];
__device__ float g_part[2*Bb*HD*HW];              // split-K partial sums
__device__ float g_gx  [(size_t)Tt*Bb*2*HD*HW];   // x-part of gates conv (+bias)
__device__ float g_cx  [(size_t)Tt*Bb*HD*HW];     // x-part of cand conv (+bias)

// ---------------------------------------------------------------------------
// Core: 3x3 SAME conv over NCI input channels (starting at ci0), one 32x32
// image, 4 output channels per CTA, 8 px/thread (128 threads). Two input
// channels per barrier; 4 smem planes (paired double buffer), zeroed borders.
// r-outer loop: only one 10-float window row live -> low register pressure.
// Weights staged as [ci][r][oc0..3] float4 (3 taps + pad): 1 LDS.128/(r,oc).
// smem = NCI*48 + 4*PLANE floats.
// ---------------------------------------------------------------------------
template<int NCI>
__device__ __forceinline__ void conv_core(
    const float* __restrict__ in,     // [64][1024] (image base)
    const float* __restrict__ wsrc,   // per-oc row stride = wstride9 floats
    int wstride9, int ocb, int ci0,
    float acc[4][8])
{
    extern __shared__ float smem[];
    float* ws = smem;                 // NCI*48 floats
    float* pl = smem + NCI*48;        // 4*PLANE floats
    const int tid = threadIdx.x;
    const int row = tid >> 2;          // 0..31
    const int xb  = (tid & 3) << 3;    // 0,8,16,24

    // ws[((ci*3 + r)*4 + oc)*4 + tap], taps 3 real + 1 pad
    for (int i = tid; i < NCI*48; i += NT) {
        const int tap = i & 3;
        const int oc_ = (i >> 2) & 3;
        const int r_  = (i >> 4) % 3;
        const int ci_ = i / 48;
        ws[i] = (tap < 3)
              ? wsrc[(size_t)(ocb*4 + oc_)*wstride9 + (ci0 + ci_)*9 + r_*3 + tap]
              : 0.f;
    }
    for (int i = tid; i < 4*PLANE; i += NT) pl[i] = 0.f;

    const float* inp = in + (size_t)ci0*HW;
    const int goff = row*IMW + xb;
    float4 n0a = *reinterpret_cast<const float4*>(inp + goff);
    float4 n0b = *reinterpret_cast<const float4*>(inp + goff + 4);
    float4 n1a = *reinterpret_cast<const float4*>(inp + HW + goff);
    float4 n1b = *reinterpret_cast<const float4*>(inp + HW + goff + 4);
    __syncthreads();   // zero/weights visible before interior stores

    #pragma unroll 1
    for (int pr = 0; pr < NCI/2; pr++) {
        float* b0 = pl + (pr & 1)*2*PLANE;
        float* b1 = b0 + PLANE;
        {
            float* d0 = b0 + (row + 1)*SROW + xb + 1;
            d0[0]=n0a.x; d0[1]=n0a.y; d0[2]=n0a.z; d0[3]=n0a.w;
            d0[4]=n0b.x; d0[5]=n0b.y; d0[6]=n0b.z; d0[7]=n0b.w;
            float* d1 = b1 + (row + 1)*SROW + xb + 1;
            d1[0]=n1a.x; d1[1]=n1a.y; d1[2]=n1a.z; d1[3]=n1a.w;
            d1[4]=n1b.x; d1[5]=n1b.y; d1[6]=n1b.z; d1[7]=n1b.w;
        }
        __syncthreads();
        if (pr < NCI/2 - 1) {
            const float* g = inp + (2*pr + 2)*HW + goff;
            n0a = *reinterpret_cast<const float4*>(g);
            n0b = *reinterpret_cast<const float4*>(g + 4);
            n1a = *reinterpret_cast<const float4*>(g + HW);
            n1b = *reinterpret_cast<const float4*>(g + HW + 4);
        }
        #pragma unroll
        for (int half = 0; half < 2; half++) {
            const float* cur = half ? b1 : b0;
            const int ci = 2*pr + half;
            #pragma unroll
            for (int r = 0; r < 3; r++) {
                const float* s = cur + (row + r)*SROW + xb;   // 16B aligned
                float4 a  = *reinterpret_cast<const float4*>(s);
                float4 b4 = *reinterpret_cast<const float4*>(s + 4);
                float2 c2 = *reinterpret_cast<const float2*>(s + 8);
                float win[10] = {a.x,a.y,a.z,a.w,b4.x,b4.y,b4.z,b4.w,c2.x,c2.y};
                const float4* wv = reinterpret_cast<const float4*>(ws + (ci*3 + r)*16);
                #pragma unroll
                for (int oc = 0; oc < 4; oc++) {
                    float4 w = wv[oc];
                    #pragma unroll
                    for (int px = 0; px < 8; px++)
                        acc[oc][px] += win[px]*w.x + win[px+1]*w.y + win[px+2]*w.z;
                }
            }
        }
    }
}

__device__ __forceinline__ float sigmoidf_(float x) { return 1.f / (1.f + expf(-x)); }

__device__ __forceinline__ void st8(float* o, const float a[8]) {
    *reinterpret_cast<float4*>(o)     = make_float4(a[0],a[1],a[2],a[3]);
    *reinterpret_cast<float4*>(o + 4) = make_float4(a[4],a[5],a[6],a[7]);
}

// ---------------------------------------------------------------------------
// Precompute x-contributions: out[t][b][co][pix] = conv(x_{T-1-t}) + bias
// grid = (cout/4, T*B)
// ---------------------------------------------------------------------------
__global__ void __launch_bounds__(NT, 5) k_pre(
    const float* __restrict__ x0, const float* __restrict__ w, int wstride9,
    const float* __restrict__ bias, float* __restrict__ out, int cout)
{
    const int ocb = blockIdx.x, z = blockIdx.y;
    const int t = z >> 4, b = z & 15;
    const float* in = x0 + ((size_t)(b*Tt + (Tt-1-t))*Cc)*HW;

    float acc[4][8];
    #pragma unroll
    for (int oc = 0; oc < 4; oc++) {
        float bv = bias[ocb*4 + oc];
        #pragma unroll
        for (int px = 0; px < 8; px++) acc[oc][px] = bv;
    }
    conv_core<64>(in, w, wstride9, ocb, 0, acc);

    const int row = threadIdx.x >> 2, xb = (threadIdx.x & 3) << 3;
    float* o = out + ((size_t)(t*Bb + b)*cout + ocb*4)*HW + row*IMW + xb;
    #pragma unroll
    for (int oc = 0; oc < 4; oc++) st8(o + oc*HW, acc[oc]);
}

// ---------------------------------------------------------------------------
// Split-K conv partials: src image conv over ci half -> g_part[half]
// grid = (16, B, 2). src: g_h (ode) or g_rh (cand).
// ---------------------------------------------------------------------------
__global__ void __launch_bounds__(NT, 5) k_conv_p(
    const float* __restrict__ src, const float* __restrict__ w, int wstride9)
{
    const int ocb = blockIdx.x, b = blockIdx.y, half = blockIdx.z;
    const float* in = src + (size_t)b*HD*HW;

    float acc[4][8];
    #pragma unroll
    for (int oc = 0; oc < 4; oc++)
        #pragma unroll
        for (int px = 0; px < 8; px++) acc[oc][px] = 0.f;
    conv_core<32>(in, w, wstride9, ocb, half*32, acc);

    const int row = threadIdx.x >> 2, xb = (threadIdx.x & 3) << 3;
    float* o = g_part + (size_t)half*Bb*HD*HW
             + ((size_t)b*HD + ocb*4)*HW + row*IMW + xb;
    #pragma unroll
    for (int oc = 0; oc < 4; oc++) st8(o + oc*HW, acc[oc]);
}

// ---------------------------------------------------------------------------
// ODE combine: hode = h + tanh(p0+p1+bias)*dt    (elementwise, float4)
// ---------------------------------------------------------------------------
__global__ void __launch_bounds__(256) k_ode_fin(
    const float* __restrict__ bias, const float* __restrict__ ts, int step)
{
    const int i4 = blockIdx.x*256 + threadIdx.x;        // 0 .. Bb*HD*HW/4-1
    const int i  = i4*4;
    const int ch = (i >> 10) & 63;
    const float dt = (step == 0) ? -0.01f : (ts[Tt-1-step] - ts[Tt-step]);
    const float bv = bias[ch];
    float4 p0 = *reinterpret_cast<const float4*>(&g_part[i]);
    float4 p1 = *reinterpret_cast<const float4*>(&g_part[Bb*HD*HW + i]);
    float4 hv = *reinterpret_cast<const float4*>(&g_h[i]);
    float4 r;
    r.x = hv.x + tanhf(p0.x + p1.x + bv)*dt;
    r.y = hv.y + tanhf(p0.y + p1.y + bv)*dt;
    r.z = hv.z + tanhf(p0.z + p1.z + bv)*dt;
    r.w = hv.w + tanhf(p0.w + p1.w + bv)*dt;
    *reinterpret_cast<float4*>(&g_hode[i]) = r;
}

// ---------------------------------------------------------------------------
// Candidate combine + GRU update + mask:
//   c = tanh(p0+p1+cx);  h = hode + m*u*(c - hode)
// ---------------------------------------------------------------------------
__global__ void __launch_bounds__(256) k_cand_fin(
    const float* __restrict__ mask, int step)
{
    const int i4 = blockIdx.x*256 + threadIdx.x;
    const int i  = i4*4;
    const int b  = i / (HD*HW);
    const float m = mask[b*Tt + (Tt-1-step)];
    float4 p0 = *reinterpret_cast<const float4*>(&g_part[i]);
    float4 p1 = *reinterpret_cast<const float4*>(&g_part[Bb*HD*HW + i]);
    float4 cx = *reinterpret_cast<const float4*>(&g_cx[(size_t)step*Bb*HD*HW + i]);
    float4 ho = *reinterpret_cast<const float4*>(&g_hode[i]);
    float4 uu = *reinterpret_cast<const float4*>(&g_u[i]);
    float4 r;
    r.x = ho.x + m*uu.x*(tanhf(p0.x + p1.x + cx.x) - ho.x);
    r.y = ho.y + m*uu.y*(tanhf(p0.y + p1.y + cx.y) - ho.y);
    r.z = ho.z + m*uu.z*(tanhf(p0.z + p1.z + cx.z) - ho.z);
    r.w = ho.w + m*uu.w*(tanhf(p0.w + p1.w + cx.w) - ho.w);
    *reinterpret_cast<float4*>(&g_h[i]) = r;
}

// ---------------------------------------------------------------------------
// Gates: g = sigmoid(conv(h_ode)+gx).  co<64 -> rh = g*h_ode; else u = g.
// grid = (32, B)
// ---------------------------------------------------------------------------
__global__ void __launch_bounds__(NT, 5) k_gates(const float* __restrict__ w, int step)
{
    const int ocb = blockIdx.x, b = blockIdx.y;
    const float* in = g_hode + (size_t)b*HD*HW;

    float acc[4][8];
    #pragma unroll
    for (int oc = 0; oc < 4; oc++)
        #pragma unroll
        for (int px = 0; px < 8; px++) acc[oc][px] = 0.f;
    conv_core<64>(in, w, 1152, ocb, 0, acc);

    const int row = threadIdx.x >> 2, xb = (threadIdx.x & 3) << 3;
    const int co0 = ocb*4;
    const float* pre = g_gx + ((size_t)(step*Bb + b)*(2*HD) + co0)*HW + row*IMW + xb;
    #pragma unroll
    for (int oc = 0; oc < 4; oc++) {
        float g[8];
        #pragma unroll
        for (int px = 0; px < 8; px++)
            g[px] = sigmoidf_(acc[oc][px] + pre[oc*HW + px]);
        if (co0 < HD) {
            size_t ib = ((size_t)b*HD + co0 + oc)*HW + row*IMW + xb;
            #pragma unroll
            for (int px = 0; px < 8; px++) g[px] *= g_hode[ib + px];
            st8(&g_rh[ib], g);
        } else {
            size_t ib = ((size_t)b*HD + co0 - HD + oc)*HW + row*IMW + xb;
            st8(&g_u[ib], g);
        }
    }
}

// ---------------------------------------------------------------------------
// Head: z1 = relu(W1 h + b1); z2 = W2 z1 + b2; out = [z2[:64] ; |z2[64:]|]
// grid = (4, B)
// ---------------------------------------------------------------------------
__global__ void __launch_bounds__(256) k_final(
    const float* __restrict__ w1, const float* __restrict__ b1,
    const float* __restrict__ w2, const float* __restrict__ b2,
    float* __restrict__ out)
{
    extern __shared__ float smem[];
    float* w1s = smem;          // [64][64]
    float* w2s = smem + 4096;   // [128][64]
    const int tid = threadIdx.x, pb = blockIdx.x, b = blockIdx.y;
    for (int i = tid; i < 4096; i += 256) w1s[i] = w1[i];
    for (int i = tid; i < 8192; i += 256) w2s[i] = w2[i];
    __syncthreads();

    const int pix = pb*256 + tid;
    float z1[64];
    #pragma unroll
    for (int co = 0; co < 64; co++) z1[co] = b1[co];
    for (int ci = 0; ci < 64; ci++) {
        float hv = g_h[((size_t)b*HD + ci)*HW + pix];
        #pragma unroll
        for (int co = 0; co < 64; co++) z1[co] += w1s[co*64 + ci]*hv;
    }
    #pragma unroll
    for (int co = 0; co < 64; co++) z1[co] = fmaxf(z1[co], 0.f);

    for (int co2 = 0; co2 < 128; co2++) {
        float a = b2[co2];
        #pragma unroll
        for (int ci = 0; ci < 64; ci++) a += w2s[co2*64 + ci]*z1[ci];
        if (co2 < 64)
            out[((size_t)b*HD + co2)*HW + pix] = a;
        else
            out[(size_t)Bb*HD*HW + ((size_t)b*HD + (co2 - 64))*HW + pix] = fabsf(a);
    }
}

// ---------------------------------------------------------------------------
extern "C" void kernel_launch(void* const* d_in, const int* in_sizes, int n_in,
                              void* d_out, int out_size)
{
    const float* input   = (const float*)d_in[0];
    const float* ts      = (const float*)d_in[1];
    const float* mask    = (const float*)d_in[2];
    const float* w_gates = (const float*)d_in[3];
    const float* b_gates = (const float*)d_in[4];
    const float* w_can   = (const float*)d_in[5];
    const float* b_can   = (const float*)d_in[6];
    const float* w_ode   = (const float*)d_in[7];
    const float* b_ode   = (const float*)d_in[8];
    const float* w_t1    = (const float*)d_in[9];
    const float* b_t1    = (const float*)d_in[10];
    const float* w_t2    = (const float*)d_in[11];
    const float* b_t2    = (const float*)d_in[12];
    float* out = (float*)d_out;

    float *hptr, *gxp, *cxp, *hode, *rh;
    cudaGetSymbolAddress((void**)&hptr, g_h);
    cudaGetSymbolAddress((void**)&gxp,  g_gx);
    cudaGetSymbolAddress((void**)&cxp,  g_cx);
    cudaGetSymbolAddress((void**)&hode, g_hode);
    cudaGetSymbolAddress((void**)&rh,   g_rh);

    cudaMemsetAsync(hptr, 0, (size_t)Bb*HD*HW*sizeof(float));

    const int SM64 = (64*48 + 4*PLANE) * (int)sizeof(float);  // 31872 B
    const int SM32 = (32*48 + 4*PLANE) * (int)sizeof(float);  // 25728 B
    const int NFIN = Bb*HD*HW/4/256;                          // 1024 CTAs

    k_pre<<<dim3(32, Tt*Bb), NT, SM64>>>(input, w_gates, 1152, b_gates, gxp, 2*HD);
    k_pre<<<dim3(16, Tt*Bb), NT, SM64>>>(input, w_can,   1152, b_can,   cxp, HD);

    for (int s = 0; s < Tt; s++) {
        k_conv_p<<<dim3(16, Bb, 2), NT, SM32>>>(hptr, w_ode, 576);
        k_ode_fin<<<NFIN, 256>>>(b_ode, ts, s);
        k_gates<<<dim3(32, Bb), NT, SM64>>>(w_gates + 64*9, s);
        k_conv_p<<<dim3(16, Bb, 2), NT, SM32>>>(rh, w_can + 64*9, 1152);
        k_cand_fin<<<NFIN, 256>>>(mask, s);
    }

    k_final<<<dim3(4, Bb), 256, 12288*(int)sizeof(float)>>>(w_t1, b_t1, w_t2, b_t2, out);
}